// round 8
// baseline (speedup 1.0000x reference)
#include <cuda_runtime.h>
#include <cuda_bf16.h>

#define NE_C 100000
#define NEP_C 100096              // NE rounded up to 128-row tiles (782 tiles)
#define NR_C 1000
#define DD   128
#define UU   128
#define E_C  500000
#define GRID_GEMM 152

// ---------------- scratch (__device__ globals, allocation-free) ----------------
__device__ float g_EW1[NE_C * UU];
__device__ float g_EW3[NE_C * UU];
__device__ float g_RW2[NR_C * UU];
__device__ float g_sA[NE_C];
__device__ float g_sB[NE_C];
__device__ float g_sR[NR_C];
__device__ int   g_cnt[NE_C];
__device__ int   g_off[NE_C + 1];
__device__ int   g_cur[NE_C];
__device__ int   g_csum[128];
__device__ int2  g_edge[E_C];
// precomputed bf16 hi/lo splits
__device__ unsigned short g_Bh[256 * 128];     // [W1|W3]^T: [u][k]
__device__ unsigned short g_Bl[256 * 128];
__device__ unsigned short g_Ah[NEP_C * 128];   // Eemb: [row][k], zero-padded rows
__device__ unsigned short g_Al[NEP_C * 128];

// ---------------------------------------------------------------------------
__device__ __forceinline__ void split1(float x, unsigned short& hi, unsigned short& lo) {
    __nv_bfloat16 hx = __float2bfloat16(x);
    __nv_bfloat16 lx = __float2bfloat16(x - __bfloat162float(hx));
    hi = __bfloat16_as_ushort(hx);
    lo = __bfloat16_as_ushort(lx);
}
__device__ __forceinline__ void split2(float x, float y, unsigned& hi, unsigned& lo) {
    __nv_bfloat16 hx = __float2bfloat16(x), hy = __float2bfloat16(y);
    __nv_bfloat16 lx = __float2bfloat16(x - __bfloat162float(hx));
    __nv_bfloat16 ly = __float2bfloat16(y - __bfloat162float(hy));
    hi = ((unsigned)__bfloat16_as_ushort(hy) << 16) | (unsigned)__bfloat16_as_ushort(hx);
    lo = ((unsigned)__bfloat16_as_ushort(ly) << 16) | (unsigned)__bfloat16_as_ushort(lx);
}

__device__ __forceinline__ unsigned smem_u32(const void* p) {
    unsigned a;
    asm("{ .reg .u64 t; cvta.to.shared.u64 t, %1; cvt.u32.u64 %0, t; }" : "=r"(a) : "l"(p));
    return a;
}
#define CP_ASYNC16(dst, src) \
    asm volatile("cp.async.cg.shared.global [%0], [%1], 16;" :: "r"(dst), "l"(src))
#define CP_COMMIT() asm volatile("cp.async.commit_group;")
#define CP_WAIT1()  asm volatile("cp.async.wait_group 1;" ::: "memory")

// K1: fused prep: zero cnt + W split + A split (streaming, coalesced)
__global__ void k_prep(const float* __restrict__ W, const float* __restrict__ Eemb,
                       int ne, int nquads) {
    int id = blockIdx.x * blockDim.x + threadIdx.x;
    if (id < ne) g_cnt[id] = 0;
    if (id < 8192) {
        int half = id >> 12;
        int rem = id & 4095;
        int k = rem >> 5;
        int u4 = (rem & 31) * 4;
        const float* src = W + (size_t)(half ? (256 + k) : k) * UU + u4;
        float4 v = *(const float4*)src;
        int ubase = half * 128 + u4;
        unsigned short h, l;
        split1(v.x, h, l); g_Bh[(ubase + 0) * 128 + k] = h; g_Bl[(ubase + 0) * 128 + k] = l;
        split1(v.y, h, l); g_Bh[(ubase + 1) * 128 + k] = h; g_Bl[(ubase + 1) * 128 + k] = l;
        split1(v.z, h, l); g_Bh[(ubase + 2) * 128 + k] = h; g_Bl[(ubase + 2) * 128 + k] = l;
        split1(v.w, h, l); g_Bh[(ubase + 3) * 128 + k] = h; g_Bl[(ubase + 3) * 128 + k] = l;
    }
    if (id < nquads) {               // nquads = npad_rows * 32
        int row = id >> 5, q = id & 31;
        float4 v = make_float4(0.f, 0.f, 0.f, 0.f);
        if (row < ne) v = *(const float4*)(Eemb + (size_t)row * DD + q * 4);
        unsigned h0, l0, h1, l1;
        split2(v.x, v.y, h0, l0);
        split2(v.z, v.w, h1, l1);
        ((uint2*)g_Ah)[(size_t)row * 32 + q] = make_uint2(h0, h1);
        ((uint2*)g_Al)[(size_t)row * 32 + q] = make_uint2(l0, l1);
    }
}

// K2: RW2[j,:] = R[j,:] @ W2 ; sR[j] = RW2[j,:] . a + a_b   (block per relation)
__global__ void k_rw2(const float* __restrict__ R, const float* __restrict__ W,
                      const float* __restrict__ a, const float* __restrict__ a_b) {
    __shared__ float r_sh[DD];
    __shared__ float red[4];
    int j = blockIdx.x;
    int u = threadIdx.x;
    r_sh[u] = R[j * DD + u];
    __syncthreads();
    float acc = 0.0f;
    const float* Wp = W + 128 * UU + u;
#pragma unroll 8
    for (int k = 0; k < DD; k++) acc += r_sh[k] * Wp[k * UU];
    g_RW2[j * UU + u] = acc;
    float p = acc * a[u];
#pragma unroll
    for (int o = 16; o > 0; o >>= 1) p += __shfl_down_sync(0xffffffffu, p, o);
    if ((u & 31) == 0) red[u >> 5] = p;
    __syncthreads();
    if (u == 0) g_sR[j] = red[0] + red[1] + red[2] + red[3] + a_b[0];
}

// ---------------------------------------------------------------------------
// K4: persistent pipelined tensor-core GEMM (pre-split bf16, fp32 accum)
// Work unit = (half, tile); A double-buffered via cp.async, no in-kernel convert.
#define SSTR  272
#define SA_SZ 34816                 // one 128-row buffer (hi or lo)
#define SB_H  139264                // after 2 stages x (hi+lo)
#define SB_L  174080
#define SAVEC 208896
#define SDOT  209408
#define SM_TOT 209920

__device__ __forceinline__ void mma16816(float* d, const unsigned* a, const unsigned* b) {
    asm volatile(
        "mma.sync.aligned.m16n8k16.row.col.f32.bf16.bf16.f32 "
        "{%0,%1,%2,%3}, {%4,%5,%6,%7}, {%8,%9}, {%0,%1,%2,%3};"
        : "+f"(d[0]), "+f"(d[1]), "+f"(d[2]), "+f"(d[3])
        : "r"(a[0]), "r"(a[1]), "r"(a[2]), "r"(a[3]), "r"(b[0]), "r"(b[1]));
}

__global__ void __launch_bounds__(256, 1)
k_gemm_mma(const float* __restrict__ a, int ne, int ntiles) {
    extern __shared__ char sm[];
    unsigned smb = smem_u32(sm);
    int tid = threadIdx.x, wid = tid >> 5, lane = tid & 31;
    int warp_m = wid & 1, warp_n = wid >> 1;   // 2 m-warps x 4 n-warps (64x32 warp tile)
    int g = lane >> 2, t4 = lane & 3;
    int nunits = ntiles * 2;

    if (tid < 128) ((float*)(sm + SAVEC))[tid] = a[tid];

    // issue stage for first unit into buffer 0
    {
        int u0 = blockIdx.x;
        if (u0 < nunits) {
            int tile = (u0 >= ntiles) ? (u0 - ntiles) : u0;
            size_t rbase = (size_t)tile * 128 * 128;
#pragma unroll
            for (int it = 0; it < 8; it++) {
                int idx = it * 256 + tid;          // 2048 chunks of 16B per buffer
                int row = idx >> 4, c = idx & 15;
                unsigned doff = row * SSTR + c * 16;
                const unsigned short* sh = g_Ah + rbase + row * 128 + c * 8;
                const unsigned short* sl = g_Al + rbase + row * 128 + c * 8;
                CP_ASYNC16(smb + doff, sh);
                CP_ASYNC16(smb + SA_SZ + doff, sl);
            }
        }
        CP_COMMIT();
    }

    const float* av = (const float*)(sm + SAVEC);
    float* sdot = (float*)(sm + SDOT);
    int cur_half = -1;
    int pbuf = 0;

    for (int u = blockIdx.x; u < nunits; u += GRID_GEMM) {
        int half = (u >= ntiles) ? 1 : 0;
        int tile = u - half * ntiles;
        int row0 = tile * 128;

        // issue stage for next unit into the other buffer
        {
            int nu = u + GRID_GEMM;
            if (nu < nunits) {
                int ntile = (nu >= ntiles) ? (nu - ntiles) : nu;
                size_t rbase = (size_t)ntile * 128 * 128;
                unsigned sb = smb + (pbuf ^ 1) * 2 * SA_SZ;
#pragma unroll
                for (int it = 0; it < 8; it++) {
                    int idx = it * 256 + tid;
                    int row = idx >> 4, c = idx & 15;
                    unsigned doff = row * SSTR + c * 16;
                    CP_ASYNC16(sb + doff, g_Ah + rbase + row * 128 + c * 8);
                    CP_ASYNC16(sb + SA_SZ + doff, g_Al + rbase + row * 128 + c * 8);
                }
            }
            CP_COMMIT();
        }

        // B fill on half transition (region disjoint from in-flight A stages)
        if (half != cur_half) {
#pragma unroll
            for (int it = 0; it < 8; it++) {
                int idx = it * 256 + tid;       // 2048 uint4
                int ur = idx >> 4, c = idx & 15;
                uint4 vh = ((const uint4*)g_Bh)[(half * 128 + ur) * 16 + c];
                uint4 vl = ((const uint4*)g_Bl)[(half * 128 + ur) * 16 + c];
                *(uint4*)(sm + SB_H + ur * SSTR + c * 16) = vh;
                *(uint4*)(sm + SB_L + ur * SSTR + c * 16) = vl;
            }
            cur_half = half;
        }

        CP_WAIT1();                 // current unit's stage complete (next still in flight)
        __syncthreads();
        if (tid < 128) sdot[tid] = 0.0f;

        const char* sa = sm + pbuf * 2 * SA_SZ;

        // ---- mainloop: warp tile 64x32, 8 k-steps, 3 mma terms ----
        float acc[4][4][4];
#pragma unroll
        for (int i = 0; i < 4; i++)
#pragma unroll
            for (int j = 0; j < 4; j++)
#pragma unroll
                for (int q = 0; q < 4; q++) acc[i][j][q] = 0.f;

#pragma unroll
        for (int ks = 0; ks < 8; ks++) {
            int kc = ks * 16 + t4 * 2;
            unsigned ah[4][4], al[4][4];
#pragma unroll
            for (int i = 0; i < 4; i++) {
                int r = warp_m * 64 + i * 16 + g;
                ah[i][0] = *(unsigned*)(sa + r * SSTR + kc * 2);
                ah[i][1] = *(unsigned*)(sa + (r + 8) * SSTR + kc * 2);
                ah[i][2] = *(unsigned*)(sa + r * SSTR + (kc + 8) * 2);
                ah[i][3] = *(unsigned*)(sa + (r + 8) * SSTR + (kc + 8) * 2);
                al[i][0] = *(unsigned*)(sa + SA_SZ + r * SSTR + kc * 2);
                al[i][1] = *(unsigned*)(sa + SA_SZ + (r + 8) * SSTR + kc * 2);
                al[i][2] = *(unsigned*)(sa + SA_SZ + r * SSTR + (kc + 8) * 2);
                al[i][3] = *(unsigned*)(sa + SA_SZ + (r + 8) * SSTR + (kc + 8) * 2);
            }
#pragma unroll
            for (int j = 0; j < 4; j++) {
                int ur = warp_n * 32 + j * 8 + g;
                unsigned bh[2], bl[2];
                bh[0] = *(unsigned*)(sm + SB_H + ur * SSTR + kc * 2);
                bh[1] = *(unsigned*)(sm + SB_H + ur * SSTR + (kc + 8) * 2);
                bl[0] = *(unsigned*)(sm + SB_L + ur * SSTR + kc * 2);
                bl[1] = *(unsigned*)(sm + SB_L + ur * SSTR + (kc + 8) * 2);
#pragma unroll
                for (int i = 0; i < 4; i++) {
                    mma16816(acc[i][j], ah[i], bh);
                    mma16816(acc[i][j], al[i], bh);
                    mma16816(acc[i][j], ah[i], bl);
                }
            }
        }

        // ---- epilogue: write EW half, fused dot with a ----
        float* base = half ? g_EW3 : g_EW1;
#pragma unroll
        for (int i = 0; i < 4; i++) {
            int rl0 = warp_m * 64 + i * 16 + g;
            float p0 = 0.f, p1 = 0.f;
#pragma unroll
            for (int j = 0; j < 4; j++) {
                int c = warp_n * 32 + j * 8 + t4 * 2;
                int row_g0 = row0 + rl0;
                if (row_g0 < ne)
                    *(float2*)(base + (size_t)row_g0 * UU + c) =
                        make_float2(acc[i][j][0], acc[i][j][1]);
                int row_g1 = row_g0 + 8;
                if (row_g1 < ne)
                    *(float2*)(base + (size_t)row_g1 * UU + c) =
                        make_float2(acc[i][j][2], acc[i][j][3]);
                p0 += acc[i][j][0] * av[c] + acc[i][j][1] * av[c + 1];
                p1 += acc[i][j][2] * av[c] + acc[i][j][3] * av[c + 1];
            }
            p0 += __shfl_xor_sync(0xffffffffu, p0, 1);
            p0 += __shfl_xor_sync(0xffffffffu, p0, 2);
            p1 += __shfl_xor_sync(0xffffffffu, p1, 1);
            p1 += __shfl_xor_sync(0xffffffffu, p1, 2);
            if (t4 == 0) {
                atomicAdd(&sdot[rl0], p0);
                atomicAdd(&sdot[rl0 + 8], p1);
            }
        }
        __syncthreads();
        if (tid < 128 && row0 + tid < ne) {
            if (half) g_sB[row0 + tid] = sdot[tid];
            else      g_sA[row0 + tid] = sdot[tid];
        }
        __syncthreads();
        pbuf ^= 1;
    }
}

// ---------------------------------------------------------------------------
// Counting sort of edges by h
__global__ void k_hist(const int* __restrict__ h, int E) {
    int e = blockIdx.x * blockDim.x + threadIdx.x;
    if (e < E) atomicAdd(&g_cnt[h[e]], 1);
}
__global__ void k_scanA(int ne) {
    __shared__ int warp_s[8];
    int tid = threadIdx.x;
    int base = blockIdx.x * 1024;
    int lane = tid & 31, w = tid >> 5;
    int v[4], s = 0;
#pragma unroll
    for (int i = 0; i < 4; i++) {
        int idx = base + tid * 4 + i;
        v[i] = (idx < ne) ? g_cnt[idx] : 0;
        s += v[i];
    }
    int x = s;
#pragma unroll
    for (int o = 1; o < 32; o <<= 1) {
        int y = __shfl_up_sync(0xffffffffu, x, o);
        if (lane >= o) x += y;
    }
    if (lane == 31) warp_s[w] = x;
    __syncthreads();
    if (w == 0) {
        int ws = (lane < 8) ? warp_s[lane] : 0;
#pragma unroll
        for (int o = 1; o < 8; o <<= 1) {
            int y = __shfl_up_sync(0xffffffffu, ws, o);
            if (lane >= o) ws += y;
        }
        if (lane < 8) warp_s[lane] = ws;
    }
    __syncthreads();
    int excl = x - s + (w > 0 ? warp_s[w - 1] : 0);
    int run = excl;
#pragma unroll
    for (int i = 0; i < 4; i++) {
        int idx = base + tid * 4 + i;
        if (idx < ne) g_off[idx] = run;
        run += v[i];
    }
    if (tid == 0) g_csum[blockIdx.x] = warp_s[7];
}
__global__ void k_scanB(int nch) {
    __shared__ int warp_s[4];
    int tid = threadIdx.x, lane = tid & 31, w = tid >> 5;
    int v = (tid < nch) ? g_csum[tid] : 0;
    int x = v;
#pragma unroll
    for (int o = 1; o < 32; o <<= 1) {
        int y = __shfl_up_sync(0xffffffffu, x, o);
        if (lane >= o) x += y;
    }
    if (lane == 31) warp_s[w] = x;
    __syncthreads();
    if (w == 0 && lane < 4) {
        int ws = warp_s[lane];
#pragma unroll
        for (int o = 1; o < 4; o <<= 1) {
            int y = __shfl_up_sync(0x0000000fu, ws, o);
            if (lane >= o) ws += y;
        }
        warp_s[lane] = ws;
    }
    __syncthreads();
    int excl = x - v + (w > 0 ? warp_s[w - 1] : 0);
    if (tid < nch) g_csum[tid] = excl;
}
__global__ void k_scanC(int ne, int E) {
    int i = blockIdx.x * blockDim.x + threadIdx.x;
    if (i < ne) {
        int o = g_off[i] + g_csum[i >> 10];
        g_off[i] = o;
        g_cur[i] = o;
    }
    if (i == 0) g_off[ne] = E;
}
__global__ void k_scatter(const int* __restrict__ h, const int* __restrict__ r,
                          const int* __restrict__ t, int E) {
    int e = blockIdx.x * blockDim.x + threadIdx.x;
    if (e >= E) return;
    int pos = atomicAdd(&g_cur[h[e]], 1);
    g_edge[pos] = make_int2(r[e], t[e]);
}

// ---------------------------------------------------------------------------
// Aggregation: warp per node, single fused pass.
__global__ void __launch_bounds__(256)
k_agg(float* __restrict__ out, const float* __restrict__ bias, int ne) {
    int warp = (blockIdx.x * blockDim.x + threadIdx.x) >> 5;
    int lane = threadIdx.x & 31;
    if (warp >= ne) return;
    int start = g_off[warp], end = g_off[warp + 1];
    float4 bv = ((const float4*)bias)[lane];
    float4 o;
    if (end > start) {
        float sAn = g_sA[warp];
        float denom = 0.f;
        float4 acc = make_float4(0.f, 0.f, 0.f, 0.f);
#pragma unroll 2
        for (int e = start; e < end; e++) {
            int2 ed = g_edge[e];
            float s = sAn + g_sR[ed.x] + g_sB[ed.y];
            float sc = (s >= 0.f) ? s : 0.04f * s;
            float es = __expf(sc);
            denom += es;
            float4 rv = ((const float4*)(g_RW2 + (size_t)ed.x * UU))[lane];
            float4 tv = ((const float4*)(g_EW3 + (size_t)ed.y * UU))[lane];
            acc.x += es * (rv.x + tv.x);
            acc.y += es * (rv.y + tv.y);
            acc.z += es * (rv.z + tv.z);
            acc.w += es * (rv.w + tv.w);
        }
        float inv = 1.f / denom;
        float4 ew = ((const float4*)(g_EW1 + (size_t)warp * UU))[lane];
        o = make_float4(acc.x * inv + ew.x + bv.x, acc.y * inv + ew.y + bv.y,
                        acc.z * inv + ew.z + bv.z, acc.w * inv + ew.w + bv.w);
    } else {
        o = bv;
    }
    o.x = fmaxf(o.x, 0.f); o.y = fmaxf(o.y, 0.f);
    o.z = fmaxf(o.z, 0.f); o.w = fmaxf(o.w, 0.f);
    ((float4*)(out + (size_t)warp * UU))[lane] = o;
}

// ---------------------------------------------------------------------------
extern "C" void kernel_launch(void* const* d_in, const int* in_sizes, int n_in,
                              void* d_out, int out_size) {
    const int*   h    = (const int*)d_in[0];
    const int*   r    = (const int*)d_in[1];
    const int*   t    = (const int*)d_in[2];
    const float* Eemb = (const float*)d_in[3];
    const float* Remb = (const float*)d_in[4];
    const float* W    = (const float*)d_in[5];
    const float* a    = (const float*)d_in[6];
    const float* ab   = (const float*)d_in[7];
    const float* bias = (const float*)d_in[8];
    float* out = (float*)d_out;

    int E  = in_sizes[0];
    int ne = in_sizes[3] / DD;
    int nr = in_sizes[4] / DD;
    int ntiles = (ne + 127) / 128;
    int nchunks = (ne + 1023) / 1024;
    int nquads = ntiles * 128 * 32;   // padded rows * 32 quads/row

    cudaFuncSetAttribute(k_gemm_mma, cudaFuncAttributeMaxDynamicSharedMemorySize, SM_TOT);

    k_prep     <<<(nquads + 255) / 256, 256>>>(W, Eemb, ne, nquads);
    k_rw2      <<<nr, 128>>>(Remb, W, a, ab);
    k_gemm_mma <<<GRID_GEMM, 256, SM_TOT>>>(a, ne, ntiles);
    k_hist     <<<(E + 255) / 256, 256>>>(h, E);
    k_scanA    <<<nchunks, 256>>>(ne);
    k_scanB    <<<1, 128>>>(nchunks);
    k_scanC    <<<(ne + 255) / 256, 256>>>(ne, E);
    k_scatter  <<<(E + 255) / 256, 256>>>(h, r, t, E);
    k_agg      <<<(ne + 7) / 8, 256>>>(out, bias, ne);
}

// round 9
// speedup vs baseline: 1.0084x; 1.0084x over previous
#include <cuda_runtime.h>
#include <cuda_bf16.h>

#define NE_C 100000
#define NEP_C 100096              // NE rounded up to 128-row tiles (782 tiles)
#define NR_C 1000
#define DD   128
#define UU   128
#define E_C  500000
#define GRID_GEMM 152

// ---------------- scratch (__device__ globals, allocation-free) ----------------
__device__ float g_EW1[NE_C * UU];
__device__ float g_EW3[NE_C * UU];
__device__ float g_RW2[NR_C * UU];
__device__ float g_sA[NE_C];
__device__ float g_sB[NE_C];
__device__ float g_sR[NR_C];
__device__ int   g_cnt[NE_C];
__device__ int   g_off[NE_C + 1];
__device__ int   g_cur[NE_C];
__device__ int   g_csum[128];
__device__ int2  g_edge[E_C];
// precomputed bf16 hi/lo splits
__device__ unsigned short g_Bh[256 * 128];     // [W1|W3]^T: [u][k]
__device__ unsigned short g_Bl[256 * 128];
__device__ unsigned short g_Ah[NEP_C * 128];   // Eemb: [row][k], zero-padded rows
__device__ unsigned short g_Al[NEP_C * 128];

// ---------------------------------------------------------------------------
__device__ __forceinline__ void split1(float x, unsigned short& hi, unsigned short& lo) {
    __nv_bfloat16 hx = __float2bfloat16(x);
    __nv_bfloat16 lx = __float2bfloat16(x - __bfloat162float(hx));
    hi = __bfloat16_as_ushort(hx);
    lo = __bfloat16_as_ushort(lx);
}
__device__ __forceinline__ void split2(float x, float y, unsigned& hi, unsigned& lo) {
    __nv_bfloat16 hx = __float2bfloat16(x), hy = __float2bfloat16(y);
    __nv_bfloat16 lx = __float2bfloat16(x - __bfloat162float(hx));
    __nv_bfloat16 ly = __float2bfloat16(y - __bfloat162float(hy));
    hi = ((unsigned)__bfloat16_as_ushort(hy) << 16) | (unsigned)__bfloat16_as_ushort(hx);
    lo = ((unsigned)__bfloat16_as_ushort(ly) << 16) | (unsigned)__bfloat16_as_ushort(lx);
}

__device__ __forceinline__ unsigned smem_u32(const void* p) {
    unsigned a;
    asm("{ .reg .u64 t; cvta.to.shared.u64 t, %1; cvt.u32.u64 %0, t; }" : "=r"(a) : "l"(p));
    return a;
}
#define CP_ASYNC16(dst, src) \
    asm volatile("cp.async.cg.shared.global [%0], [%1], 16;" :: "r"(dst), "l"(src))
#define CP_COMMIT() asm volatile("cp.async.commit_group;")
#define CP_WAIT1()  asm volatile("cp.async.wait_group 1;" ::: "memory")
#define LDMX4(r0, r1, r2, r3, addr) \
    asm volatile("ldmatrix.sync.aligned.m8n8.x4.shared.b16 {%0,%1,%2,%3}, [%4];" \
                 : "=r"(r0), "=r"(r1), "=r"(r2), "=r"(r3) : "r"(addr))

// K2': RW2 + sR, plus zero g_cnt (runs before k_prep's fused histogram)
__global__ void k_rw2(const float* __restrict__ R, const float* __restrict__ W,
                      const float* __restrict__ a, const float* __restrict__ a_b, int ne) {
    __shared__ float r_sh[DD];
    __shared__ float red[4];
    int j = blockIdx.x;
    int u = threadIdx.x;
    int id = j * 128 + u;
    if (id < ne) g_cnt[id] = 0;
    r_sh[u] = R[j * DD + u];
    __syncthreads();
    float acc = 0.0f;
    const float* Wp = W + 128 * UU + u;
#pragma unroll 8
    for (int k = 0; k < DD; k++) acc += r_sh[k] * Wp[k * UU];
    g_RW2[j * UU + u] = acc;
    float p = acc * a[u];
#pragma unroll
    for (int o = 16; o > 0; o >>= 1) p += __shfl_down_sync(0xffffffffu, p, o);
    if ((u & 31) == 0) red[u >> 5] = p;
    __syncthreads();
    if (u == 0) g_sR[j] = red[0] + red[1] + red[2] + red[3] + a_b[0];
}

// K1: fused prep: W split + A split + edge histogram (cnt zeroed by k_rw2)
__global__ void k_prep(const float* __restrict__ W, const float* __restrict__ Eemb,
                       const int* __restrict__ h, int ne, int E, int nquads) {
    int id = blockIdx.x * blockDim.x + threadIdx.x;
    if (id < E) atomicAdd(&g_cnt[h[id]], 1);
    if (id < 8192) {
        int half = id >> 12;
        int rem = id & 4095;
        int k = rem >> 5;
        int u4 = (rem & 31) * 4;
        const float* src = W + (size_t)(half ? (256 + k) : k) * UU + u4;
        float4 v = *(const float4*)src;
        int ubase = half * 128 + u4;
        unsigned short hh, ll;
        split1(v.x, hh, ll); g_Bh[(ubase + 0) * 128 + k] = hh; g_Bl[(ubase + 0) * 128 + k] = ll;
        split1(v.y, hh, ll); g_Bh[(ubase + 1) * 128 + k] = hh; g_Bl[(ubase + 1) * 128 + k] = ll;
        split1(v.z, hh, ll); g_Bh[(ubase + 2) * 128 + k] = hh; g_Bl[(ubase + 2) * 128 + k] = ll;
        split1(v.w, hh, ll); g_Bh[(ubase + 3) * 128 + k] = hh; g_Bl[(ubase + 3) * 128 + k] = ll;
    }
    if (id < nquads) {               // nquads = npad_rows * 32
        int row = id >> 5, q = id & 31;
        float4 v = make_float4(0.f, 0.f, 0.f, 0.f);
        if (row < ne) v = *(const float4*)(Eemb + (size_t)row * DD + q * 4);
        unsigned h0, l0, h1, l1;
        split2(v.x, v.y, h0, l0);
        split2(v.z, v.w, h1, l1);
        ((uint2*)g_Ah)[(size_t)row * 32 + q] = make_uint2(h0, h1);
        ((uint2*)g_Al)[(size_t)row * 32 + q] = make_uint2(l0, l1);
    }
}

// ---------------------------------------------------------------------------
// K4: persistent pipelined tensor-core GEMM (pre-split bf16, fp32 accum)
// 512 threads, 16 warps (4x4 grid, warp tile 32x32), ldmatrix fragment loads,
// A double-buffered via cp.async. Work unit = (half, tile).
#define SSTR  272
#define SA_SZ 34816                 // one 128-row buffer (hi or lo)
#define SB_H  139264                // after 2 stages x (hi+lo)
#define SB_L  174080
#define SAVEC 208896
#define SDOT  209408
#define SM_TOT 209920

__device__ __forceinline__ void mma16816(float* d, const unsigned* a, const unsigned* b) {
    asm volatile(
        "mma.sync.aligned.m16n8k16.row.col.f32.bf16.bf16.f32 "
        "{%0,%1,%2,%3}, {%4,%5,%6,%7}, {%8,%9}, {%0,%1,%2,%3};"
        : "+f"(d[0]), "+f"(d[1]), "+f"(d[2]), "+f"(d[3])
        : "r"(a[0]), "r"(a[1]), "r"(a[2]), "r"(a[3]), "r"(b[0]), "r"(b[1]));
}

__global__ void __launch_bounds__(512, 1)
k_gemm_mma(const float* __restrict__ a, int ne, int ntiles) {
    extern __shared__ char sm[];
    unsigned smb = smem_u32(sm);
    int tid = threadIdx.x, wid = tid >> 5, lane = tid & 31;
    int warp_m = wid & 3, warp_n = wid >> 2;   // 4 m-warps x 4 n-warps (32x32 tile)
    int g = lane >> 2, t4 = lane & 3;
    int nunits = ntiles * 2;

    if (tid < 128) {
        ((float*)(sm + SAVEC))[tid] = a[tid];
        ((float*)(sm + SDOT))[tid] = 0.0f;
    }

    // per-thread ldmatrix address components
    unsigned aoff = (unsigned)((warp_m * 32 + (lane & 15)) * SSTR + (lane >> 4) * 16);
    unsigned boff = (unsigned)((warp_n * 32 + (lane & 7) + ((lane >> 4) << 3)) * SSTR
                               + (((lane >> 3) & 1) << 4));

    // issue stage for first unit into buffer 0
    {
        int u0 = blockIdx.x;
        if (u0 < nunits) {
            int tile = (u0 >= ntiles) ? (u0 - ntiles) : u0;
            size_t rbase = (size_t)tile * 128 * 128;
#pragma unroll
            for (int it = 0; it < 4; it++) {
                int idx = it * 512 + tid;          // 2048 chunks of 16B per buffer
                int row = idx >> 4, c = idx & 15;
                unsigned doff = row * SSTR + c * 16;
                CP_ASYNC16(smb + doff, g_Ah + rbase + row * 128 + c * 8);
                CP_ASYNC16(smb + SA_SZ + doff, g_Al + rbase + row * 128 + c * 8);
            }
        }
        CP_COMMIT();
    }

    const float* av = (const float*)(sm + SAVEC);
    float* sdot = (float*)(sm + SDOT);
    int cur_half = -1;
    int pbuf = 0;

    for (int u = blockIdx.x; u < nunits; u += GRID_GEMM) {
        int half = (u >= ntiles) ? 1 : 0;
        int tile = u - half * ntiles;
        int row0 = tile * 128;

        // issue stage for next unit into the other buffer
        {
            int nu = u + GRID_GEMM;
            if (nu < nunits) {
                int ntile = (nu >= ntiles) ? (nu - ntiles) : nu;
                size_t rbase = (size_t)ntile * 128 * 128;
                unsigned sb = smb + (pbuf ^ 1) * 2 * SA_SZ;
#pragma unroll
                for (int it = 0; it < 4; it++) {
                    int idx = it * 512 + tid;
                    int row = idx >> 4, c = idx & 15;
                    unsigned doff = row * SSTR + c * 16;
                    CP_ASYNC16(sb + doff, g_Ah + rbase + row * 128 + c * 8);
                    CP_ASYNC16(sb + SA_SZ + doff, g_Al + rbase + row * 128 + c * 8);
                }
            }
            CP_COMMIT();
        }

        // B fill on half transition (disjoint from in-flight A stages)
        if (half != cur_half) {
#pragma unroll
            for (int it = 0; it < 4; it++) {
                int idx = it * 512 + tid;       // 2048 uint4
                int ur = idx >> 4, c = idx & 15;
                uint4 vh = ((const uint4*)g_Bh)[(half * 128 + ur) * 16 + c];
                uint4 vl = ((const uint4*)g_Bl)[(half * 128 + ur) * 16 + c];
                *(uint4*)(sm + SB_H + ur * SSTR + c * 16) = vh;
                *(uint4*)(sm + SB_L + ur * SSTR + c * 16) = vl;
            }
            cur_half = half;
        }

        CP_WAIT1();                 // current unit's stage complete (next in flight)
        __syncthreads();

        unsigned sa_hi = smb + pbuf * 2 * SA_SZ + aoff;
        unsigned sa_lo = sa_hi + SA_SZ;
        unsigned sb_hi = smb + SB_H + boff;
        unsigned sb_lo = smb + SB_L + boff;

        // ---- mainloop: 8 k-steps, warp tile 32x32, 3 mma terms ----
        float acc[2][4][4];
#pragma unroll
        for (int i = 0; i < 2; i++)
#pragma unroll
            for (int j = 0; j < 4; j++)
#pragma unroll
                for (int q = 0; q < 4; q++) acc[i][j][q] = 0.f;

#pragma unroll
        for (int ks = 0; ks < 8; ks++) {
            unsigned kso = ks * 32;
            unsigned ah[2][4], al[2][4], bh[2][4], bl[2][4];
#pragma unroll
            for (int i = 0; i < 2; i++) {
                LDMX4(ah[i][0], ah[i][1], ah[i][2], ah[i][3], sa_hi + i * 16 * SSTR + kso);
                LDMX4(al[i][0], al[i][1], al[i][2], al[i][3], sa_lo + i * 16 * SSTR + kso);
            }
#pragma unroll
            for (int jp = 0; jp < 2; jp++) {
                LDMX4(bh[jp][0], bh[jp][1], bh[jp][2], bh[jp][3], sb_hi + jp * 16 * SSTR + kso);
                LDMX4(bl[jp][0], bl[jp][1], bl[jp][2], bl[jp][3], sb_lo + jp * 16 * SSTR + kso);
            }
#pragma unroll
            for (int jp = 0; jp < 2; jp++)
#pragma unroll
                for (int jj = 0; jj < 2; jj++) {
                    int j = jp * 2 + jj;
#pragma unroll
                    for (int i = 0; i < 2; i++) {
                        mma16816(acc[i][j], ah[i], &bh[jp][jj * 2]);
                        mma16816(acc[i][j], al[i], &bh[jp][jj * 2]);
                        mma16816(acc[i][j], ah[i], &bl[jp][jj * 2]);
                    }
                }
        }

        // ---- epilogue: write EW half, fused dot with a ----
        float* base = half ? g_EW3 : g_EW1;
#pragma unroll
        for (int i = 0; i < 2; i++) {
            int rl0 = warp_m * 32 + i * 16 + g;
            float p0 = 0.f, p1 = 0.f;
#pragma unroll
            for (int j = 0; j < 4; j++) {
                int c = warp_n * 32 + j * 8 + t4 * 2;
                int row_g0 = row0 + rl0;
                if (row_g0 < ne)
                    *(float2*)(base + (size_t)row_g0 * UU + c) =
                        make_float2(acc[i][j][0], acc[i][j][1]);
                int row_g1 = row_g0 + 8;
                if (row_g1 < ne)
                    *(float2*)(base + (size_t)row_g1 * UU + c) =
                        make_float2(acc[i][j][2], acc[i][j][3]);
                p0 += acc[i][j][0] * av[c] + acc[i][j][1] * av[c + 1];
                p1 += acc[i][j][2] * av[c] + acc[i][j][3] * av[c + 1];
            }
            p0 += __shfl_xor_sync(0xffffffffu, p0, 1);
            p0 += __shfl_xor_sync(0xffffffffu, p0, 2);
            p1 += __shfl_xor_sync(0xffffffffu, p1, 1);
            p1 += __shfl_xor_sync(0xffffffffu, p1, 2);
            if (t4 == 0) {
                atomicAdd(&sdot[rl0], p0);
                atomicAdd(&sdot[rl0 + 8], p1);
            }
        }
        __syncthreads();
        if (tid < 128) {
            if (row0 + tid < ne) {
                if (half) g_sB[row0 + tid] = sdot[tid];
                else      g_sA[row0 + tid] = sdot[tid];
            }
            sdot[tid] = 0.0f;       // reset for next unit (ordered by final sync)
        }
        __syncthreads();
        pbuf ^= 1;
    }
}

// ---------------------------------------------------------------------------
// Prefix scan of per-node counts (3 small kernels)
__global__ void k_scanA(int ne) {
    __shared__ int warp_s[8];
    int tid = threadIdx.x;
    int base = blockIdx.x * 1024;
    int lane = tid & 31, w = tid >> 5;
    int v[4], s = 0;
#pragma unroll
    for (int i = 0; i < 4; i++) {
        int idx = base + tid * 4 + i;
        v[i] = (idx < ne) ? g_cnt[idx] : 0;
        s += v[i];
    }
    int x = s;
#pragma unroll
    for (int o = 1; o < 32; o <<= 1) {
        int y = __shfl_up_sync(0xffffffffu, x, o);
        if (lane >= o) x += y;
    }
    if (lane == 31) warp_s[w] = x;
    __syncthreads();
    if (w == 0) {
        int ws = (lane < 8) ? warp_s[lane] : 0;
#pragma unroll
        for (int o = 1; o < 8; o <<= 1) {
            int y = __shfl_up_sync(0xffffffffu, ws, o);
            if (lane >= o) ws += y;
        }
        if (lane < 8) warp_s[lane] = ws;
    }
    __syncthreads();
    int excl = x - s + (w > 0 ? warp_s[w - 1] : 0);
    int run = excl;
#pragma unroll
    for (int i = 0; i < 4; i++) {
        int idx = base + tid * 4 + i;
        if (idx < ne) g_off[idx] = run;
        run += v[i];
    }
    if (tid == 0) g_csum[blockIdx.x] = warp_s[7];
}
__global__ void k_scanB(int nch) {
    __shared__ int warp_s[4];
    int tid = threadIdx.x, lane = tid & 31, w = tid >> 5;
    int v = (tid < nch) ? g_csum[tid] : 0;
    int x = v;
#pragma unroll
    for (int o = 1; o < 32; o <<= 1) {
        int y = __shfl_up_sync(0xffffffffu, x, o);
        if (lane >= o) x += y;
    }
    if (lane == 31) warp_s[w] = x;
    __syncthreads();
    if (w == 0 && lane < 4) {
        int ws = warp_s[lane];
#pragma unroll
        for (int o = 1; o < 4; o <<= 1) {
            int y = __shfl_up_sync(0x0000000fu, ws, o);
            if (lane >= o) ws += y;
        }
        warp_s[lane] = ws;
    }
    __syncthreads();
    int excl = x - v + (w > 0 ? warp_s[w - 1] : 0);
    if (tid < nch) g_csum[tid] = excl;
}
__global__ void k_scanC(int ne, int E) {
    int i = blockIdx.x * blockDim.x + threadIdx.x;
    if (i < ne) {
        int o = g_off[i] + g_csum[i >> 10];
        g_off[i] = o;
        g_cur[i] = o;
    }
    if (i == 0) g_off[ne] = E;
}
__global__ void k_scatter(const int* __restrict__ h, const int* __restrict__ r,
                          const int* __restrict__ t, int E) {
    int e = blockIdx.x * blockDim.x + threadIdx.x;
    if (e >= E) return;
    int pos = atomicAdd(&g_cur[h[e]], 1);
    g_edge[pos] = make_int2(r[e], t[e]);
}

// ---------------------------------------------------------------------------
// Aggregation: warp per node, single fused pass.
__global__ void __launch_bounds__(256)
k_agg(float* __restrict__ out, const float* __restrict__ bias, int ne) {
    int warp = (blockIdx.x * blockDim.x + threadIdx.x) >> 5;
    int lane = threadIdx.x & 31;
    if (warp >= ne) return;
    int start = g_off[warp], end = g_off[warp + 1];
    float4 bv = ((const float4*)bias)[lane];
    float4 o;
    if (end > start) {
        float sAn = g_sA[warp];
        float denom = 0.f;
        float4 acc = make_float4(0.f, 0.f, 0.f, 0.f);
#pragma unroll 2
        for (int e = start; e < end; e++) {
            int2 ed = g_edge[e];
            float s = sAn + g_sR[ed.x] + g_sB[ed.y];
            float sc = (s >= 0.f) ? s : 0.04f * s;
            float es = __expf(sc);
            denom += es;
            float4 rv = ((const float4*)(g_RW2 + (size_t)ed.x * UU))[lane];
            float4 tv = ((const float4*)(g_EW3 + (size_t)ed.y * UU))[lane];
            acc.x += es * (rv.x + tv.x);
            acc.y += es * (rv.y + tv.y);
            acc.z += es * (rv.z + tv.z);
            acc.w += es * (rv.w + tv.w);
        }
        float inv = 1.f / denom;
        float4 ew = ((const float4*)(g_EW1 + (size_t)warp * UU))[lane];
        o = make_float4(acc.x * inv + ew.x + bv.x, acc.y * inv + ew.y + bv.y,
                        acc.z * inv + ew.z + bv.z, acc.w * inv + ew.w + bv.w);
    } else {
        o = bv;
    }
    o.x = fmaxf(o.x, 0.f); o.y = fmaxf(o.y, 0.f);
    o.z = fmaxf(o.z, 0.f); o.w = fmaxf(o.w, 0.f);
    ((float4*)(out + (size_t)warp * UU))[lane] = o;
}

// ---------------------------------------------------------------------------
extern "C" void kernel_launch(void* const* d_in, const int* in_sizes, int n_in,
                              void* d_out, int out_size) {
    const int*   h    = (const int*)d_in[0];
    const int*   r    = (const int*)d_in[1];
    const int*   t    = (const int*)d_in[2];
    const float* Eemb = (const float*)d_in[3];
    const float* Remb = (const float*)d_in[4];
    const float* W    = (const float*)d_in[5];
    const float* a    = (const float*)d_in[6];
    const float* ab   = (const float*)d_in[7];
    const float* bias = (const float*)d_in[8];
    float* out = (float*)d_out;

    int E  = in_sizes[0];
    int ne = in_sizes[3] / DD;
    int nr = in_sizes[4] / DD;
    int ntiles = (ne + 127) / 128;
    int nchunks = (ne + 1023) / 1024;
    int nquads = ntiles * 128 * 32;   // padded rows * 32 quads/row

    cudaFuncSetAttribute(k_gemm_mma, cudaFuncAttributeMaxDynamicSharedMemorySize, SM_TOT);

    k_rw2      <<<nr, 128>>>(Remb, W, a, ab, ne);
    k_prep     <<<(nquads + 255) / 256, 256>>>(W, Eemb, h, ne, E, nquads);
    k_gemm_mma <<<GRID_GEMM, 512, SM_TOT>>>(a, ne, ntiles);
    k_scanA    <<<nchunks, 256>>>(ne);
    k_scanB    <<<1, 128>>>(nchunks);
    k_scanC    <<<(ne + 255) / 256, 256>>>(ne, E);
    k_scatter  <<<(E + 255) / 256, 256>>>(h, r, t, E);
    k_agg      <<<(ne + 7) / 8, 256>>>(out, bias, ne);
}

// round 11
// speedup vs baseline: 1.1286x; 1.1192x over previous
#include <cuda_runtime.h>
#include <cuda_fp16.h>

#define NE_C 100000
#define NEP_C 100096              // NE rounded up to 128-row tiles (782 tiles)
#define NR_C 1000
#define DD   128
#define UU   128
#define E_C  500000
#define GRID_GEMM 152

// ---------------- scratch (__device__ globals, allocation-free) ----------------
__device__ float g_EW1[NE_C * UU];
__device__ float g_EW3[NE_C * UU];
__device__ float g_RW2[NR_C * UU];
__device__ float g_sA[NE_C];
__device__ float g_sB[NE_C];
__device__ float g_sR[NR_C];
__device__ int   g_cnt[NE_C];
__device__ int   g_off[NE_C + 1];
__device__ int   g_cur[NE_C];
__device__ int   g_csum[128];
__device__ int2  g_edge[E_C];
// precomputed fp16 data: A rounded once; B split hi/lo
__device__ unsigned short g_Af[NEP_C * 128];   // Eemb fp16: [row][k], zero-padded
__device__ unsigned short g_Bh[256 * 128];     // [W1|W3]^T fp16 hi: [u][k]
__device__ unsigned short g_Bl[256 * 128];     // fp16 lo residual

// ---------------------------------------------------------------------------
__device__ __forceinline__ unsigned smem_u32(const void* p) {
    unsigned a;
    asm("{ .reg .u64 t; cvta.to.shared.u64 t, %1; cvt.u32.u64 %0, t; }" : "=r"(a) : "l"(p));
    return a;
}
#define CP_ASYNC16(dst, src) \
    asm volatile("cp.async.cg.shared.global [%0], [%1], 16;" :: "r"(dst), "l"(src))
#define CP_COMMIT() asm volatile("cp.async.commit_group;")
#define CP_WAIT1()  asm volatile("cp.async.wait_group 1;" ::: "memory")
#define LDMX4(r0, r1, r2, r3, addr) \
    asm volatile("ldmatrix.sync.aligned.m8n8.x4.shared.b16 {%0,%1,%2,%3}, [%4];" \
                 : "=r"(r0), "=r"(r1), "=r"(r2), "=r"(r3) : "r"(addr))

// K2': RW2 + sR (exact fp32), plus zero g_cnt (runs before k_prep's histogram)
__global__ void k_rw2(const float* __restrict__ R, const float* __restrict__ W,
                      const float* __restrict__ a, const float* __restrict__ a_b, int ne) {
    __shared__ float r_sh[DD];
    __shared__ float red[4];
    int j = blockIdx.x;
    int u = threadIdx.x;
    int id = j * 128 + u;
    if (id < ne) g_cnt[id] = 0;
    r_sh[u] = R[j * DD + u];
    __syncthreads();
    float acc = 0.0f;
    const float* Wp = W + 128 * UU + u;
#pragma unroll 8
    for (int k = 0; k < DD; k++) acc += r_sh[k] * Wp[k * UU];
    g_RW2[j * UU + u] = acc;
    float p = acc * a[u];
#pragma unroll
    for (int o = 16; o > 0; o >>= 1) p += __shfl_down_sync(0xffffffffu, p, o);
    if ((u & 31) == 0) red[u >> 5] = p;
    __syncthreads();
    if (u == 0) g_sR[j] = red[0] + red[1] + red[2] + red[3] + a_b[0];
}

// K1: fused prep: W fp16 hi/lo split + A fp16 round + edge histogram
__global__ void k_prep(const float* __restrict__ W, const float* __restrict__ Eemb,
                       const int* __restrict__ h, int ne, int E, int nquads) {
    int id = blockIdx.x * blockDim.x + threadIdx.x;
    if (id < E) atomicAdd(&g_cnt[h[id]], 1);
    if (id < 8192) {
        int half_ = id >> 12;
        int rem = id & 4095;
        int k = rem >> 5;
        int u4 = (rem & 31) * 4;
        const float* src = W + (size_t)(half_ ? (256 + k) : k) * UU + u4;
        float4 v = *(const float4*)src;
        int ubase = half_ * 128 + u4;
        float vv[4] = {v.x, v.y, v.z, v.w};
#pragma unroll
        for (int q = 0; q < 4; q++) {
            __half hh = __float2half_rn(vv[q]);
            __half ll = __float2half_rn(vv[q] - __half2float(hh));
            g_Bh[(ubase + q) * 128 + k] = __half_as_ushort(hh);
            g_Bl[(ubase + q) * 128 + k] = __half_as_ushort(ll);
        }
    }
    if (id < nquads) {               // nquads = npad_rows * 32
        int row = id >> 5, q = id & 31;
        float4 v = make_float4(0.f, 0.f, 0.f, 0.f);
        if (row < ne) v = *(const float4*)(Eemb + (size_t)row * DD + q * 4);
        unsigned p0 = ((unsigned)__half_as_ushort(__float2half_rn(v.y)) << 16)
                    | (unsigned)__half_as_ushort(__float2half_rn(v.x));
        unsigned p1 = ((unsigned)__half_as_ushort(__float2half_rn(v.w)) << 16)
                    | (unsigned)__half_as_ushort(__float2half_rn(v.z));
        ((uint2*)g_Af)[(size_t)row * 32 + q] = make_uint2(p0, p1);
    }
}

// ---------------------------------------------------------------------------
// K4: persistent pipelined tensor-core GEMM (fp16 2-term: Af*Bhi + Af*Blo)
// 512 threads, 16 warps (4x4, warp tile 32x32), ldmatrix, A double-buffered.
// Work unit = (half, tile): half 0 -> EW1/sA, half 1 -> EW3/sB.
#define SSTR  272
#define SA_SZ 34816                 // one 128-row fp16 A buffer
#define SB_H  69632                 // after 2 A stages
#define SB_L  104448
#define SAVEC 139264
#define SDOT  139776
#define SM_TOT 140288

__device__ __forceinline__ void mma16816(float* d, const unsigned* a, const unsigned* b) {
    asm volatile(
        "mma.sync.aligned.m16n8k16.row.col.f32.f16.f16.f32 "
        "{%0,%1,%2,%3}, {%4,%5,%6,%7}, {%8,%9}, {%0,%1,%2,%3};"
        : "+f"(d[0]), "+f"(d[1]), "+f"(d[2]), "+f"(d[3])
        : "r"(a[0]), "r"(a[1]), "r"(a[2]), "r"(a[3]), "r"(b[0]), "r"(b[1]));
}

__global__ void __launch_bounds__(512, 1)
k_gemm_mma(const float* __restrict__ a, int ne, int ntiles) {
    extern __shared__ char sm[];
    unsigned smb = smem_u32(sm);
    int tid = threadIdx.x, wid = tid >> 5, lane = tid & 31;
    int warp_m = wid & 3, warp_n = wid >> 2;   // 4 m-warps x 4 n-warps (32x32 tile)
    int g = lane >> 2, t4 = lane & 3;
    int nunits = ntiles * 2;

    if (tid < 128) {
        ((float*)(sm + SAVEC))[tid] = a[tid];
        ((float*)(sm + SDOT))[tid] = 0.0f;
    }

    // per-thread ldmatrix address components
    unsigned aoff = (unsigned)((warp_m * 32 + (lane & 15)) * SSTR + (lane >> 4) * 16);
    unsigned boff = (unsigned)((warp_n * 32 + (lane & 7) + ((lane >> 4) << 3)) * SSTR
                               + (((lane >> 3) & 1) << 4));

    // issue stage for first unit into buffer 0 (2048 x 16B chunks)
    {
        int u0 = blockIdx.x;
        if (u0 < nunits) {
            int tile = (u0 >= ntiles) ? (u0 - ntiles) : u0;
            size_t rbase = (size_t)tile * 128 * 128;
#pragma unroll
            for (int it = 0; it < 4; it++) {
                int idx = it * 512 + tid;
                int row = idx >> 4, c = idx & 15;
                CP_ASYNC16(smb + row * SSTR + c * 16, g_Af + rbase + row * 128 + c * 8);
            }
        }
        CP_COMMIT();
    }

    const float* av = (const float*)(sm + SAVEC);
    float* sdot = (float*)(sm + SDOT);
    int cur_half = -1;
    int pbuf = 0;

    for (int u = blockIdx.x; u < nunits; u += GRID_GEMM) {
        int half_ = (u >= ntiles) ? 1 : 0;
        int tile = u - half_ * ntiles;
        int row0 = tile * 128;

        // issue stage for next unit into the other buffer
        {
            int nu = u + GRID_GEMM;
            if (nu < nunits) {
                int ntile = (nu >= ntiles) ? (nu - ntiles) : nu;
                size_t rbase = (size_t)ntile * 128 * 128;
                unsigned sb = smb + (pbuf ^ 1) * SA_SZ;
#pragma unroll
                for (int it = 0; it < 4; it++) {
                    int idx = it * 512 + tid;
                    int row = idx >> 4, c = idx & 15;
                    CP_ASYNC16(sb + row * SSTR + c * 16, g_Af + rbase + row * 128 + c * 8);
                }
            }
            CP_COMMIT();
        }

        // B fill on half transition (disjoint from in-flight A stages)
        if (half_ != cur_half) {
#pragma unroll
            for (int it = 0; it < 4; it++) {
                int idx = it * 512 + tid;       // 2048 uint4
                int ur = idx >> 4, c = idx & 15;
                uint4 vh = ((const uint4*)g_Bh)[(half_ * 128 + ur) * 16 + c];
                uint4 vl = ((const uint4*)g_Bl)[(half_ * 128 + ur) * 16 + c];
                *(uint4*)(sm + SB_H + ur * SSTR + c * 16) = vh;
                *(uint4*)(sm + SB_L + ur * SSTR + c * 16) = vl;
            }
            cur_half = half_;
        }

        CP_WAIT1();                 // current unit's stage complete (next in flight)
        __syncthreads();

        unsigned sa_f  = smb + pbuf * SA_SZ + aoff;
        unsigned sb_hi = smb + SB_H + boff;
        unsigned sb_lo = smb + SB_L + boff;

        // ---- mainloop: 8 k-steps, warp tile 32x32, 2 mma terms ----
        float acc[2][4][4];
#pragma unroll
        for (int i = 0; i < 2; i++)
#pragma unroll
            for (int j = 0; j < 4; j++)
#pragma unroll
                for (int q = 0; q < 4; q++) acc[i][j][q] = 0.f;

#pragma unroll
        for (int ks = 0; ks < 8; ks++) {
            unsigned kso = ks * 32;
            unsigned af[2][4], bh[2][4], bl[2][4];
#pragma unroll
            for (int i = 0; i < 2; i++)
                LDMX4(af[i][0], af[i][1], af[i][2], af[i][3], sa_f + i * 16 * SSTR + kso);
#pragma unroll
            for (int jp = 0; jp < 2; jp++) {
                LDMX4(bh[jp][0], bh[jp][1], bh[jp][2], bh[jp][3], sb_hi + jp * 16 * SSTR + kso);
                LDMX4(bl[jp][0], bl[jp][1], bl[jp][2], bl[jp][3], sb_lo + jp * 16 * SSTR + kso);
            }
#pragma unroll
            for (int jp = 0; jp < 2; jp++)
#pragma unroll
                for (int jj = 0; jj < 2; jj++) {
                    int j = jp * 2 + jj;
#pragma unroll
                    for (int i = 0; i < 2; i++) {
                        mma16816(acc[i][j], af[i], &bh[jp][jj * 2]);
                        mma16816(acc[i][j], af[i], &bl[jp][jj * 2]);
                    }
                }
        }

        // ---- epilogue: write EW half, fused dot with a ----
        float* base = half_ ? g_EW3 : g_EW1;
#pragma unroll
        for (int i = 0; i < 2; i++) {
            int rl0 = warp_m * 32 + i * 16 + g;
            float p0 = 0.f, p1 = 0.f;
#pragma unroll
            for (int j = 0; j < 4; j++) {
                int c = warp_n * 32 + j * 8 + t4 * 2;
                int row_g0 = row0 + rl0;
                if (row_g0 < ne)
                    *(float2*)(base + (size_t)row_g0 * UU + c) =
                        make_float2(acc[i][j][0], acc[i][j][1]);
                int row_g1 = row_g0 + 8;
                if (row_g1 < ne)
                    *(float2*)(base + (size_t)row_g1 * UU + c) =
                        make_float2(acc[i][j][2], acc[i][j][3]);
                p0 += acc[i][j][0] * av[c] + acc[i][j][1] * av[c + 1];
                p1 += acc[i][j][2] * av[c] + acc[i][j][3] * av[c + 1];
            }
            p0 += __shfl_xor_sync(0xffffffffu, p0, 1);
            p0 += __shfl_xor_sync(0xffffffffu, p0, 2);
            p1 += __shfl_xor_sync(0xffffffffu, p1, 1);
            p1 += __shfl_xor_sync(0xffffffffu, p1, 2);
            if (t4 == 0) {
                atomicAdd(&sdot[rl0], p0);
                atomicAdd(&sdot[rl0 + 8], p1);
            }
        }
        __syncthreads();
        if (tid < 128) {
            if (row0 + tid < ne) {
                if (half_) g_sB[row0 + tid] = sdot[tid];
                else       g_sA[row0 + tid] = sdot[tid];
            }
            sdot[tid] = 0.0f;       // reset for next unit (ordered by final sync)
        }
        __syncthreads();
        pbuf ^= 1;
    }
}

// ---------------------------------------------------------------------------
// Prefix scan of per-node counts
__global__ void k_scanA(int ne) {
    __shared__ int warp_s[8];
    int tid = threadIdx.x;
    int base = blockIdx.x * 1024;
    int lane = tid & 31, w = tid >> 5;
    int v[4], s = 0;
#pragma unroll
    for (int i = 0; i < 4; i++) {
        int idx = base + tid * 4 + i;
        v[i] = (idx < ne) ? g_cnt[idx] : 0;
        s += v[i];
    }
    int x = s;
#pragma unroll
    for (int o = 1; o < 32; o <<= 1) {
        int y = __shfl_up_sync(0xffffffffu, x, o);
        if (lane >= o) x += y;
    }
    if (lane == 31) warp_s[w] = x;
    __syncthreads();
    if (w == 0) {
        int ws = (lane < 8) ? warp_s[lane] : 0;
#pragma unroll
        for (int o = 1; o < 8; o <<= 1) {
            int y = __shfl_up_sync(0xffffffffu, ws, o);
            if (lane >= o) ws += y;
        }
        if (lane < 8) warp_s[lane] = ws;
    }
    __syncthreads();
    int excl = x - s + (w > 0 ? warp_s[w - 1] : 0);
    int run = excl;
#pragma unroll
    for (int i = 0; i < 4; i++) {
        int idx = base + tid * 4 + i;
        if (idx < ne) g_off[idx] = run;
        run += v[i];
    }
    if (tid == 0) g_csum[blockIdx.x] = warp_s[7];
}
__global__ void k_scanB(int nch) {
    __shared__ int warp_s[4];
    int tid = threadIdx.x, lane = tid & 31, w = tid >> 5;
    int v = (tid < nch) ? g_csum[tid] : 0;
    int x = v;
#pragma unroll
    for (int o = 1; o < 32; o <<= 1) {
        int y = __shfl_up_sync(0xffffffffu, x, o);
        if (lane >= o) x += y;
    }
    if (lane == 31) warp_s[w] = x;
    __syncthreads();
    if (w == 0 && lane < 4) {
        int ws = warp_s[lane];
#pragma unroll
        for (int o = 1; o < 4; o <<= 1) {
            int y = __shfl_up_sync(0x0000000fu, ws, o);
            if (lane >= o) ws += y;
        }
        warp_s[lane] = ws;
    }
    __syncthreads();
    int excl = x - v + (w > 0 ? warp_s[w - 1] : 0);
    if (tid < nch) g_csum[tid] = excl;
}
__global__ void k_scanC(int ne, int E) {
    int i = blockIdx.x * blockDim.x + threadIdx.x;
    if (i < ne) {
        int o = g_off[i] + g_csum[i >> 10];
        g_off[i] = o;
        g_cur[i] = o;
    }
    if (i == 0) g_off[ne] = E;
}
__global__ void k_scatter(const int* __restrict__ h, const int* __restrict__ r,
                          const int* __restrict__ t, int E) {
    int e = blockIdx.x * blockDim.x + threadIdx.x;
    if (e >= E) return;
    int pos = atomicAdd(&g_cur[h[e]], 1);
    g_edge[pos] = make_int2(r[e], t[e]);
}

// ---------------------------------------------------------------------------
// Aggregation: warp per node, single fused pass.
__global__ void __launch_bounds__(256)
k_agg(float* __restrict__ out, const float* __restrict__ bias, int ne) {
    int warp = (blockIdx.x * blockDim.x + threadIdx.x) >> 5;
    int lane = threadIdx.x & 31;
    if (warp >= ne) return;
    int start = g_off[warp], end = g_off[warp + 1];
    float4 bv = ((const float4*)bias)[lane];
    float4 o;
    if (end > start) {
        float sAn = g_sA[warp];
        float denom = 0.f;
        float4 acc = make_float4(0.f, 0.f, 0.f, 0.f);
#pragma unroll 2
        for (int e = start; e < end; e++) {
            int2 ed = g_edge[e];
            float s = sAn + g_sR[ed.x] + g_sB[ed.y];
            float sc = (s >= 0.f) ? s : 0.04f * s;
            float es = __expf(sc);
            denom += es;
            float4 rv = ((const float4*)(g_RW2 + (size_t)ed.x * UU))[lane];
            float4 tv = ((const float4*)(g_EW3 + (size_t)ed.y * UU))[lane];
            acc.x += es * (rv.x + tv.x);
            acc.y += es * (rv.y + tv.y);
            acc.z += es * (rv.z + tv.z);
            acc.w += es * (rv.w + tv.w);
        }
        float inv = 1.f / denom;
        float4 ew = ((const float4*)(g_EW1 + (size_t)warp * UU))[lane];
        o = make_float4(acc.x * inv + ew.x + bv.x, acc.y * inv + ew.y + bv.y,
                        acc.z * inv + ew.z + bv.z, acc.w * inv + ew.w + bv.w);
    } else {
        o = bv;
    }
    o.x = fmaxf(o.x, 0.f); o.y = fmaxf(o.y, 0.f);
    o.z = fmaxf(o.z, 0.f); o.w = fmaxf(o.w, 0.f);
    ((float4*)(out + (size_t)warp * UU))[lane] = o;
}

// ---------------------------------------------------------------------------
extern "C" void kernel_launch(void* const* d_in, const int* in_sizes, int n_in,
                              void* d_out, int out_size) {
    const int*   h    = (const int*)d_in[0];
    const int*   r    = (const int*)d_in[1];
    const int*   t    = (const int*)d_in[2];
    const float* Eemb = (const float*)d_in[3];
    const float* Remb = (const float*)d_in[4];
    const float* W    = (const float*)d_in[5];
    const float* a    = (const float*)d_in[6];
    const float* ab   = (const float*)d_in[7];
    const float* bias = (const float*)d_in[8];
    float* out = (float*)d_out;

    int E  = in_sizes[0];
    int ne = in_sizes[3] / DD;
    int nr = in_sizes[4] / DD;
    int ntiles = (ne + 127) / 128;
    int nchunks = (ne + 1023) / 1024;
    int nquads = ntiles * 128 * 32;

    cudaFuncSetAttribute(k_gemm_mma, cudaFuncAttributeMaxDynamicSharedMemorySize, SM_TOT);

    k_rw2      <<<nr, 128>>>(Remb, W, a, ab, ne);
    k_prep     <<<(nquads + 255) / 256, 256>>>(W, Eemb, h, ne, E, nquads);
    k_gemm_mma <<<GRID_GEMM, 512, SM_TOT>>>(a, ne, ntiles);
    k_scanA    <<<nchunks, 256>>>(ne);
    k_scanB    <<<1, 128>>>(nchunks);
    k_scanC    <<<(ne + 255) / 256, 256>>>(ne, E);
    k_scatter  <<<(E + 255) / 256, 256>>>(h, r, t, E);
    k_agg      <<<(ne + 7) / 8, 256>>>(out, bias, ne);
}

// round 12
// speedup vs baseline: 1.2714x; 1.1265x over previous
#include <cuda_runtime.h>
#include <cuda_fp16.h>

#define NE_C 100000
#define NEP_C 100096              // NE rounded up to 128-row tiles (782 tiles)
#define NR_C 1000
#define DD   128
#define UU   128
#define E_C  500000
#define GRID_GEMM 152

// ---------------- scratch (__device__ globals, allocation-free) ----------------
__device__ float    g_EW1[NE_C * UU];
__device__ unsigned g_EW3h[NE_C * 64];     // half2-packed EW3 rows
__device__ unsigned g_RW2h[NR_C * 64];     // half2-packed RW2 rows
__device__ float g_sA[NE_C];
__device__ float g_sB[NE_C];
__device__ float g_sR[NR_C];
__device__ int   g_cnt[NE_C];
__device__ int   g_off[NE_C + 1];
__device__ int   g_cur[NE_C];
__device__ int   g_csum[128];
__device__ int2  g_edge[E_C];
// precomputed fp16 data: A rounded once; B split hi/lo
__device__ unsigned short g_Af[NEP_C * 128];   // Eemb fp16: [row][k], zero-padded
__device__ unsigned short g_Bh[256 * 128];     // [W1|W3]^T fp16 hi: [u][k]
__device__ unsigned short g_Bl[256 * 128];     // fp16 lo residual

// ---------------------------------------------------------------------------
__device__ __forceinline__ unsigned smem_u32(const void* p) {
    unsigned a;
    asm("{ .reg .u64 t; cvta.to.shared.u64 t, %1; cvt.u32.u64 %0, t; }" : "=r"(a) : "l"(p));
    return a;
}
__device__ __forceinline__ unsigned pack_h2(float lo, float hi) {
    __half2 h = __floats2half2_rn(lo, hi);
    return *(unsigned*)&h;
}
#define CP_ASYNC16(dst, src) \
    asm volatile("cp.async.cg.shared.global [%0], [%1], 16;" :: "r"(dst), "l"(src))
#define CP_COMMIT() asm volatile("cp.async.commit_group;")
#define CP_WAIT1()  asm volatile("cp.async.wait_group 1;" ::: "memory")
#define LDMX4(r0, r1, r2, r3, addr) \
    asm volatile("ldmatrix.sync.aligned.m8n8.x4.shared.b16 {%0,%1,%2,%3}, [%4];" \
                 : "=r"(r0), "=r"(r1), "=r"(r2), "=r"(r3) : "r"(addr))

// K2': RW2 (half2-packed) + sR (exact fp32), plus zero g_cnt
__global__ void k_rw2(const float* __restrict__ R, const float* __restrict__ W,
                      const float* __restrict__ a, const float* __restrict__ a_b, int ne) {
    __shared__ float r_sh[DD];
    __shared__ float red[4];
    int j = blockIdx.x;
    int u = threadIdx.x;
    int id = j * 128 + u;
    if (id < ne) g_cnt[id] = 0;
    r_sh[u] = R[j * DD + u];
    __syncthreads();
    float acc = 0.0f;
    const float* Wp = W + 128 * UU + u;
#pragma unroll 8
    for (int k = 0; k < DD; k++) acc += r_sh[k] * Wp[k * UU];
    // pack (even,odd) columns into half2
    float nb = __shfl_down_sync(0xffffffffu, acc, 1);
    if ((u & 1) == 0) g_RW2h[j * 64 + (u >> 1)] = pack_h2(acc, nb);
    float p = acc * a[u];
#pragma unroll
    for (int o = 16; o > 0; o >>= 1) p += __shfl_down_sync(0xffffffffu, p, o);
    if ((u & 31) == 0) red[u >> 5] = p;
    __syncthreads();
    if (u == 0) g_sR[j] = red[0] + red[1] + red[2] + red[3] + a_b[0];
}

// K1: fused prep: W fp16 hi/lo split + A fp16 round + edge histogram
__global__ void k_prep(const float* __restrict__ W, const float* __restrict__ Eemb,
                       const int* __restrict__ h, int ne, int E, int nquads) {
    int id = blockIdx.x * blockDim.x + threadIdx.x;
    if (id < E) atomicAdd(&g_cnt[h[id]], 1);
    if (id < 8192) {
        int half_ = id >> 12;
        int rem = id & 4095;
        int k = rem >> 5;
        int u4 = (rem & 31) * 4;
        const float* src = W + (size_t)(half_ ? (256 + k) : k) * UU + u4;
        float4 v = *(const float4*)src;
        int ubase = half_ * 128 + u4;
        float vv[4] = {v.x, v.y, v.z, v.w};
#pragma unroll
        for (int q = 0; q < 4; q++) {
            __half hh = __float2half_rn(vv[q]);
            __half ll = __float2half_rn(vv[q] - __half2float(hh));
            g_Bh[(ubase + q) * 128 + k] = __half_as_ushort(hh);
            g_Bl[(ubase + q) * 128 + k] = __half_as_ushort(ll);
        }
    }
    if (id < nquads) {               // nquads = npad_rows * 32
        int row = id >> 5, q = id & 31;
        float4 v = make_float4(0.f, 0.f, 0.f, 0.f);
        if (row < ne) v = *(const float4*)(Eemb + (size_t)row * DD + q * 4);
        ((uint2*)g_Af)[(size_t)row * 32 + q] =
            make_uint2(pack_h2(v.x, v.y), pack_h2(v.z, v.w));
    }
}

// ---------------------------------------------------------------------------
// K4: persistent pipelined tensor-core GEMM (fp16 2-term: Af*Bhi + Af*Blo)
// 512 threads, 16 warps (4x4, warp tile 32x32), ldmatrix, A double-buffered.
// Work unit = (half, tile): half 0 -> EW1/sA (fp32), half 1 -> EW3h/sB (half2).
#define SSTR  272
#define SA_SZ 34816                 // one 128-row fp16 A buffer
#define SB_H  69632                 // after 2 A stages
#define SB_L  104448
#define SAVEC 139264
#define SDOT  139776
#define SM_TOT 140288

__device__ __forceinline__ void mma16816(float* d, const unsigned* a, const unsigned* b) {
    asm volatile(
        "mma.sync.aligned.m16n8k16.row.col.f32.f16.f16.f32 "
        "{%0,%1,%2,%3}, {%4,%5,%6,%7}, {%8,%9}, {%0,%1,%2,%3};"
        : "+f"(d[0]), "+f"(d[1]), "+f"(d[2]), "+f"(d[3])
        : "r"(a[0]), "r"(a[1]), "r"(a[2]), "r"(a[3]), "r"(b[0]), "r"(b[1]));
}

__global__ void __launch_bounds__(512, 1)
k_gemm_mma(const float* __restrict__ a, int ne, int ntiles) {
    extern __shared__ char sm[];
    unsigned smb = smem_u32(sm);
    int tid = threadIdx.x, wid = tid >> 5, lane = tid & 31;
    int warp_m = wid & 3, warp_n = wid >> 2;   // 4 m-warps x 4 n-warps (32x32 tile)
    int g = lane >> 2, t4 = lane & 3;
    int nunits = ntiles * 2;

    if (tid < 128) {
        ((float*)(sm + SAVEC))[tid] = a[tid];
        ((float*)(sm + SDOT))[tid] = 0.0f;
    }

    unsigned aoff = (unsigned)((warp_m * 32 + (lane & 15)) * SSTR + (lane >> 4) * 16);
    unsigned boff = (unsigned)((warp_n * 32 + (lane & 7) + ((lane >> 4) << 3)) * SSTR
                               + (((lane >> 3) & 1) << 4));

    // issue stage for first unit into buffer 0 (2048 x 16B chunks)
    {
        int u0 = blockIdx.x;
        if (u0 < nunits) {
            int tile = (u0 >= ntiles) ? (u0 - ntiles) : u0;
            size_t rbase = (size_t)tile * 128 * 128;
#pragma unroll
            for (int it = 0; it < 4; it++) {
                int idx = it * 512 + tid;
                int row = idx >> 4, c = idx & 15;
                CP_ASYNC16(smb + row * SSTR + c * 16, g_Af + rbase + row * 128 + c * 8);
            }
        }
        CP_COMMIT();
    }

    const float* av = (const float*)(sm + SAVEC);
    float* sdot = (float*)(sm + SDOT);
    int cur_half = -1;
    int pbuf = 0;

    for (int u = blockIdx.x; u < nunits; u += GRID_GEMM) {
        int half_ = (u >= ntiles) ? 1 : 0;
        int tile = u - half_ * ntiles;
        int row0 = tile * 128;

        // issue stage for next unit into the other buffer
        {
            int nu = u + GRID_GEMM;
            if (nu < nunits) {
                int ntile = (nu >= ntiles) ? (nu - ntiles) : nu;
                size_t rbase = (size_t)ntile * 128 * 128;
                unsigned sb = smb + (pbuf ^ 1) * SA_SZ;
#pragma unroll
                for (int it = 0; it < 4; it++) {
                    int idx = it * 512 + tid;
                    int row = idx >> 4, c = idx & 15;
                    CP_ASYNC16(sb + row * SSTR + c * 16, g_Af + rbase + row * 128 + c * 8);
                }
            }
            CP_COMMIT();
        }

        // B fill on half transition
        if (half_ != cur_half) {
#pragma unroll
            for (int it = 0; it < 4; it++) {
                int idx = it * 512 + tid;       // 2048 uint4
                int ur = idx >> 4, c = idx & 15;
                uint4 vh = ((const uint4*)g_Bh)[(half_ * 128 + ur) * 16 + c];
                uint4 vl = ((const uint4*)g_Bl)[(half_ * 128 + ur) * 16 + c];
                *(uint4*)(sm + SB_H + ur * SSTR + c * 16) = vh;
                *(uint4*)(sm + SB_L + ur * SSTR + c * 16) = vl;
            }
            cur_half = half_;
        }

        CP_WAIT1();
        __syncthreads();

        unsigned sa_f  = smb + pbuf * SA_SZ + aoff;
        unsigned sb_hi = smb + SB_H + boff;
        unsigned sb_lo = smb + SB_L + boff;

        // ---- mainloop: 8 k-steps, warp tile 32x32, 2 mma terms ----
        float acc[2][4][4];
#pragma unroll
        for (int i = 0; i < 2; i++)
#pragma unroll
            for (int j = 0; j < 4; j++)
#pragma unroll
                for (int q = 0; q < 4; q++) acc[i][j][q] = 0.f;

#pragma unroll
        for (int ks = 0; ks < 8; ks++) {
            unsigned kso = ks * 32;
            unsigned af[2][4], bh[2][4], bl[2][4];
#pragma unroll
            for (int i = 0; i < 2; i++)
                LDMX4(af[i][0], af[i][1], af[i][2], af[i][3], sa_f + i * 16 * SSTR + kso);
#pragma unroll
            for (int jp = 0; jp < 2; jp++) {
                LDMX4(bh[jp][0], bh[jp][1], bh[jp][2], bh[jp][3], sb_hi + jp * 16 * SSTR + kso);
                LDMX4(bl[jp][0], bl[jp][1], bl[jp][2], bl[jp][3], sb_lo + jp * 16 * SSTR + kso);
            }
#pragma unroll
            for (int jp = 0; jp < 2; jp++)
#pragma unroll
                for (int jj = 0; jj < 2; jj++) {
                    int j = jp * 2 + jj;
#pragma unroll
                    for (int i = 0; i < 2; i++) {
                        mma16816(acc[i][j], af[i], &bh[jp][jj * 2]);
                        mma16816(acc[i][j], af[i], &bl[jp][jj * 2]);
                    }
                }
        }

        // ---- epilogue: write EW half (fp32 for EW1, half2 for EW3), fused dot ----
#pragma unroll
        for (int i = 0; i < 2; i++) {
            int rl0 = warp_m * 32 + i * 16 + g;
            float p0 = 0.f, p1 = 0.f;
#pragma unroll
            for (int j = 0; j < 4; j++) {
                int c = warp_n * 32 + j * 8 + t4 * 2;
                int row_g0 = row0 + rl0;
                int row_g1 = row_g0 + 8;
                if (half_) {
                    if (row_g0 < ne)
                        g_EW3h[(size_t)row_g0 * 64 + (c >> 1)] =
                            pack_h2(acc[i][j][0], acc[i][j][1]);
                    if (row_g1 < ne)
                        g_EW3h[(size_t)row_g1 * 64 + (c >> 1)] =
                            pack_h2(acc[i][j][2], acc[i][j][3]);
                } else {
                    if (row_g0 < ne)
                        *(float2*)(g_EW1 + (size_t)row_g0 * UU + c) =
                            make_float2(acc[i][j][0], acc[i][j][1]);
                    if (row_g1 < ne)
                        *(float2*)(g_EW1 + (size_t)row_g1 * UU + c) =
                            make_float2(acc[i][j][2], acc[i][j][3]);
                }
                p0 += acc[i][j][0] * av[c] + acc[i][j][1] * av[c + 1];
                p1 += acc[i][j][2] * av[c] + acc[i][j][3] * av[c + 1];
            }
            p0 += __shfl_xor_sync(0xffffffffu, p0, 1);
            p0 += __shfl_xor_sync(0xffffffffu, p0, 2);
            p1 += __shfl_xor_sync(0xffffffffu, p1, 1);
            p1 += __shfl_xor_sync(0xffffffffu, p1, 2);
            if (t4 == 0) {
                atomicAdd(&sdot[rl0], p0);
                atomicAdd(&sdot[rl0 + 8], p1);
            }
        }
        __syncthreads();
        if (tid < 128) {
            if (row0 + tid < ne) {
                if (half_) g_sB[row0 + tid] = sdot[tid];
                else       g_sA[row0 + tid] = sdot[tid];
            }
            sdot[tid] = 0.0f;
        }
        __syncthreads();
        pbuf ^= 1;
    }
}

// ---------------------------------------------------------------------------
// Prefix scan of per-node counts
__global__ void k_scanA(int ne) {
    __shared__ int warp_s[8];
    int tid = threadIdx.x;
    int base = blockIdx.x * 1024;
    int lane = tid & 31, w = tid >> 5;
    int v[4], s = 0;
#pragma unroll
    for (int i = 0; i < 4; i++) {
        int idx = base + tid * 4 + i;
        v[i] = (idx < ne) ? g_cnt[idx] : 0;
        s += v[i];
    }
    int x = s;
#pragma unroll
    for (int o = 1; o < 32; o <<= 1) {
        int y = __shfl_up_sync(0xffffffffu, x, o);
        if (lane >= o) x += y;
    }
    if (lane == 31) warp_s[w] = x;
    __syncthreads();
    if (w == 0) {
        int ws = (lane < 8) ? warp_s[lane] : 0;
#pragma unroll
        for (int o = 1; o < 8; o <<= 1) {
            int y = __shfl_up_sync(0xffffffffu, ws, o);
            if (lane >= o) ws += y;
        }
        if (lane < 8) warp_s[lane] = ws;
    }
    __syncthreads();
    int excl = x - s + (w > 0 ? warp_s[w - 1] : 0);
    int run = excl;
#pragma unroll
    for (int i = 0; i < 4; i++) {
        int idx = base + tid * 4 + i;
        if (idx < ne) g_off[idx] = run;
        run += v[i];
    }
    if (tid == 0) g_csum[blockIdx.x] = warp_s[7];
}
__global__ void k_scanB(int nch) {
    __shared__ int warp_s[4];
    int tid = threadIdx.x, lane = tid & 31, w = tid >> 5;
    int v = (tid < nch) ? g_csum[tid] : 0;
    int x = v;
#pragma unroll
    for (int o = 1; o < 32; o <<= 1) {
        int y = __shfl_up_sync(0xffffffffu, x, o);
        if (lane >= o) x += y;
    }
    if (lane == 31) warp_s[w] = x;
    __syncthreads();
    if (w == 0 && lane < 4) {
        int ws = warp_s[lane];
#pragma unroll
        for (int o = 1; o < 4; o <<= 1) {
            int y = __shfl_up_sync(0x0000000fu, ws, o);
            if (lane >= o) ws += y;
        }
        warp_s[lane] = ws;
    }
    __syncthreads();
    int excl = x - v + (w > 0 ? warp_s[w - 1] : 0);
    if (tid < nch) g_csum[tid] = excl;
}
__global__ void k_scanC(int ne, int E) {
    int i = blockIdx.x * blockDim.x + threadIdx.x;
    if (i < ne) {
        int o = g_off[i] + g_csum[i >> 10];
        g_off[i] = o;
        g_cur[i] = o;
    }
    if (i == 0) g_off[ne] = E;
}
__global__ void k_scatter(const int* __restrict__ h, const int* __restrict__ r,
                          const int* __restrict__ t, int E) {
    int e = blockIdx.x * blockDim.x + threadIdx.x;
    if (e >= E) return;
    int pos = atomicAdd(&g_cur[h[e]], 1);
    g_edge[pos] = make_int2(r[e], t[e]);
}

// ---------------------------------------------------------------------------
// Aggregation: warp per node, single fused pass, half2 gathers.
__global__ void __launch_bounds__(256)
k_agg(float* __restrict__ out, const float* __restrict__ bias, int ne) {
    int warp = (blockIdx.x * blockDim.x + threadIdx.x) >> 5;
    int lane = threadIdx.x & 31;
    if (warp >= ne) return;
    int start = g_off[warp], end = g_off[warp + 1];
    float4 bv = ((const float4*)bias)[lane];
    float4 o;
    if (end > start) {
        float sAn = g_sA[warp];
        float denom = 0.f;
        float4 acc = make_float4(0.f, 0.f, 0.f, 0.f);
#pragma unroll 2
        for (int e = start; e < end; e++) {
            int2 ed = g_edge[e];
            float s = sAn + g_sR[ed.x] + g_sB[ed.y];
            float sc = (s >= 0.f) ? s : 0.04f * s;
            float es = __expf(sc);
            denom += es;
            uint2 rv = ((const uint2*)(g_RW2h + (size_t)ed.x * 64))[lane];
            uint2 tv = ((const uint2*)(g_EW3h + (size_t)ed.y * 64))[lane];
            float2 r0 = __half22float2(*(__half2*)&rv.x);
            float2 r1 = __half22float2(*(__half2*)&rv.y);
            float2 t0 = __half22float2(*(__half2*)&tv.x);
            float2 t1 = __half22float2(*(__half2*)&tv.y);
            acc.x += es * (r0.x + t0.x);
            acc.y += es * (r0.y + t0.y);
            acc.z += es * (r1.x + t1.x);
            acc.w += es * (r1.y + t1.y);
        }
        float inv = 1.f / denom;
        float4 ew = ((const float4*)(g_EW1 + (size_t)warp * UU))[lane];
        o = make_float4(acc.x * inv + ew.x + bv.x, acc.y * inv + ew.y + bv.y,
                        acc.z * inv + ew.z + bv.z, acc.w * inv + ew.w + bv.w);
    } else {
        o = bv;
    }
    o.x = fmaxf(o.x, 0.f); o.y = fmaxf(o.y, 0.f);
    o.z = fmaxf(o.z, 0.f); o.w = fmaxf(o.w, 0.f);
    ((float4*)(out + (size_t)warp * UU))[lane] = o;
}

// ---------------------------------------------------------------------------
extern "C" void kernel_launch(void* const* d_in, const int* in_sizes, int n_in,
                              void* d_out, int out_size) {
    const int*   h    = (const int*)d_in[0];
    const int*   r    = (const int*)d_in[1];
    const int*   t    = (const int*)d_in[2];
    const float* Eemb = (const float*)d_in[3];
    const float* Remb = (const float*)d_in[4];
    const float* W    = (const float*)d_in[5];
    const float* a    = (const float*)d_in[6];
    const float* ab   = (const float*)d_in[7];
    const float* bias = (const float*)d_in[8];
    float* out = (float*)d_out;

    int E  = in_sizes[0];
    int ne = in_sizes[3] / DD;
    int nr = in_sizes[4] / DD;
    int ntiles = (ne + 127) / 128;
    int nchunks = (ne + 1023) / 1024;
    int nquads = ntiles * 128 * 32;

    cudaFuncSetAttribute(k_gemm_mma, cudaFuncAttributeMaxDynamicSharedMemorySize, SM_TOT);

    k_rw2      <<<nr, 128>>>(Remb, W, a, ab, ne);
    k_prep     <<<(nquads + 255) / 256, 256>>>(W, Eemb, h, ne, E, nquads);
    k_gemm_mma <<<GRID_GEMM, 512, SM_TOT>>>(a, ne, ntiles);
    k_scanA    <<<nchunks, 256>>>(ne);
    k_scanB    <<<1, 128>>>(nchunks);
    k_scanC    <<<(ne + 255) / 256, 256>>>(ne, E);
    k_scatter  <<<(E + 255) / 256, 256>>>(h, r, t, E);
    k_agg      <<<(ne + 7) / 8, 256>>>(out, bias, ne);
}